// round 3
// baseline (speedup 1.0000x reference)
#include <cuda_runtime.h>
#include <cuda_bf16.h>

// Problem: B=128 matrices of N=512. For each superdiagonal k (offset k+1),
// compute sample variance over its L=511-k elements, scaled = sqrt(var)*L/5,
// loss[b] = mean_k scaled. Output: loss twice (2*128 floats).
//
// Strategy: one block per batch, 1024 threads (32 warps).
//   - Diagonals grouped into 16 chunks of 32 (lane <-> diagonal within chunk).
//   - Warp w: chunk-pair j = w/4 handles chunks j and 15-j (constant total
//     trip count = 542 -> perfect inter-warp balance), row-split r = w%4
//     handles rows p ≡ r (mod 4).
//   - Loads: at row p, lanes read 32 consecutive floats at p*513 + k + 1
//     (fully coalesced, elements touched exactly once -> pure HBM stream).
//   - Per-lane register accumulation of (sum, sumsq); 4 row-split partials
//     merged with shared-memory float atomics (few thousand per block).
//   - Epilogue: per-k variance -> scaled, block tree reduction, write out.

__global__ __launch_bounds__(1024, 1)
void diag_loss_kernel(const float* __restrict__ ssmap,
                      float* __restrict__ out, int out_size) {
    constexpr int N = 512;
    constexpr int K = 510;  // number of superdiagonals (N-2)

    __shared__ float s_sum[512];
    __shared__ float s_sq[512];
    __shared__ float s_red[1024];

    const int b = blockIdx.x;
    const float* base = ssmap + (size_t)b * (N * N);
    const int tid  = threadIdx.x;
    const int w    = tid >> 5;
    const int lane = tid & 31;

    if (tid < 512) { s_sum[tid] = 0.0f; s_sq[tid] = 0.0f; }
    __syncthreads();

    const int j = w >> 2;   // chunk-pair index 0..7
    const int r = w & 3;    // row split 0..3

    #pragma unroll
    for (int cc = 0; cc < 2; ++cc) {
        const int chunk = (cc == 0) ? j : (15 - j);
        const int k = chunk * 32 + lane;      // this lane's diagonal
        const int L = 511 - k;                // valid length of diagonal k
        const int maxL = 511 - chunk * 32;    // longest diagonal in chunk (lane 0)
        const float* dp = base + (k + 1);     // row p element: dp[p*513]
        float sum = 0.0f, sq = 0.0f;

        #pragma unroll 4
        for (int p = r; p < maxL; p += 4) {
            if (p < L) {
                float x = __ldg(dp + (size_t)p * 513);
                sum += x;
                sq = fmaf(x, x, sq);
            }
        }
        if (k < K) {
            atomicAdd(&s_sum[k], sum);
            atomicAdd(&s_sq[k], sq);
        }
    }
    __syncthreads();

    // Per-diagonal statistic.
    float scaled = 0.0f;
    if (tid < K) {
        const float Lf   = (float)(511 - tid);
        const float su   = s_sum[tid];
        const float sq   = s_sq[tid];
        const float mean = su / Lf;
        float var = (sq - su * mean) / (Lf - 1.0f);
        var = fmaxf(var, 0.0f);               // guard tiny negative from rounding
        scaled = sqrtf(var) * Lf * 0.2f;      // sqrt(var) * L / 5
    }
    s_red[tid] = scaled;
    __syncthreads();

    // Block tree reduction over 1024 slots (slots >= K are zero).
    #pragma unroll
    for (int s = 512; s >= 1; s >>= 1) {
        if (tid < s) s_red[tid] += s_red[tid + s];
        __syncthreads();
    }

    if (tid == 0) {
        const float loss = s_red[0] * (1.0f / 510.0f);
        out[b] = loss;
        if (out_size >= 256) out[128 + b] = loss;  // second (stop_gradient) copy
    }
}

extern "C" void kernel_launch(void* const* d_in, const int* in_sizes, int n_in,
                              void* d_out, int out_size) {
    const float* ssmap = (const float*)d_in[0];
    float* out = (float*)d_out;
    diag_loss_kernel<<<128, 1024>>>(ssmap, out, out_size);
}